// round 13
// baseline (speedup 1.0000x reference)
#include <cuda_runtime.h>
#include <cuda_bf16.h>
#include <math.h>
#include <stdint.h>

#define T_TOK 2048
#define H_DIM 1024
#define I_DIM 1024
#define S_LEN 1024
#define B_SZ  2
#define NH    16
#define NKV   4
#define HD    64
#define NE    8
#define TCAP  2048
#define QKV_N 1536   // 1024 q + 256 k + 256 v

// ---------------- scratch ----------------
__device__ float g_x1[T_TOK * H_DIM];
__device__ float g_qkv[T_TOK * QKV_N];
__device__ float g_attn[T_TOK * NH * HD];
__device__ float g_resid[T_TOK * H_DIM];
__device__ float g_x2[T_TOK * H_DIM];
__device__ float g_moe[T_TOK * H_DIM];
__device__ float g_G[(NE + 1) * TCAP * I_DIM];   // expert 8 = shared expert
__device__ float g_U[(NE + 1) * TCAP * I_DIM];
__device__ float g_wqkv[H_DIM * QKV_N];
__device__ float g_probs[T_TOK * NE];
__device__ int   g_cnt[NE + 1];
__device__ int   g_asg_tok[(NE + 1) * TCAP];
__device__ float g_asg_w[(NE + 1) * TCAP];

__device__ __forceinline__ uint32_t f2tf(float x)
{
    uint32_t u;
    asm("cvt.rna.tf32.f32 %0, %1;" : "=r"(u) : "f"(x));
    return u;
}

__device__ __forceinline__ void mma_tf32(float* c, const uint32_t* a, uint32_t b0, uint32_t b1)
{
    asm volatile(
        "mma.sync.aligned.m16n8k8.row.col.f32.tf32.tf32.f32 "
        "{%0,%1,%2,%3},{%4,%5,%6,%7},{%8,%9},{%0,%1,%2,%3};"
        : "+f"(c[0]), "+f"(c[1]), "+f"(c[2]), "+f"(c[3])
        : "r"(a[0]), "r"(a[1]), "r"(a[2]), "r"(a[3]), "r"(b0), "r"(b1));
}

// ---------------- zero + expert-8 identity assignment (inside graph) ----------------
__global__ void zero_kernel()
{
    int i = blockIdx.x * blockDim.x + threadIdx.x;
    if (i < T_TOK * H_DIM) g_moe[i] = 0.f;
    if (i < NE) g_cnt[i] = 0;
    if (i == NE) g_cnt[NE] = TCAP;
    if (i < TCAP) g_asg_tok[NE * TCAP + i] = i;
}

// ---------------- concat wq|wk|wv -> g_wqkv [H][1536] ----------------
__global__ void concat_qkv_w(const float* __restrict__ wq, const float* __restrict__ wk,
                             const float* __restrict__ wv)
{
    int idx = blockIdx.x * blockDim.x + threadIdx.x;
    if (idx >= H_DIM * QKV_N) return;
    int r = idx / QKV_N, c = idx - r * QKV_N;
    float v;
    if (c < 1024)      v = wq[r * 1024 + c];
    else if (c < 1280) v = wk[r * 256 + (c - 1024)];
    else               v = wv[r * 256 + (c - 1280)];
    g_wqkv[idx] = v;
}

// ---------------- RMSNorm ----------------
__global__ void rmsnorm_kernel(const float* __restrict__ x, const float* __restrict__ w,
                               float* __restrict__ y)
{
    __shared__ float red[8];
    __shared__ float s_inv;
    int t = blockIdx.x;
    int tid = threadIdx.x;
    const float4* xp = (const float4*)(x + (size_t)t * H_DIM);
    float4 v = xp[tid];
    float ss = v.x * v.x + v.y * v.y + v.z * v.z + v.w * v.w;
    #pragma unroll
    for (int off = 16; off; off >>= 1) ss += __shfl_xor_sync(0xffffffffu, ss, off);
    if ((tid & 31) == 0) red[tid >> 5] = ss;
    __syncthreads();
    if (tid == 0) {
        float s = 0.f;
        #pragma unroll
        for (int i = 0; i < 8; i++) s += red[i];
        s_inv = rsqrtf(s / (float)H_DIM + 1e-6f);
    }
    __syncthreads();
    float inv = s_inv;
    const float4* wp = (const float4*)w;
    float4 wv = wp[tid];
    float4 o;
    o.x = v.x * inv * wv.x; o.y = v.y * inv * wv.y;
    o.z = v.z * inv * wv.z; o.w = v.w * inv * wv.w;
    ((float4*)(y + (size_t)t * H_DIM))[tid] = o;
}

// ---------------- tf32 TC GEMM: 128x128x16 tile, 512 thr (16 warps, 32x32/warp) ----------------
// MODE 0: C = A@B            MODE 1: C = Cadd + A@B
// MODE 2: per-expert gather rows of A via asg_tok; C row = e*TCAP + local
//         (e == NE -> shared expert, B = Bsh)
// MODE 3: per-expert A row = e*TCAP+local; atomicAdd C[tok] * asg_w  (e==NE -> Bsh)
// DUAL 1 (with MODE 2): blockIdx.z LSB selects (B,C,Bsh) vs (B2,C2,Bsh2)
template<int MODE, int DUAL>
__global__ __launch_bounds__(512)
void gemm_tc(const float* __restrict__ A, const float* __restrict__ B,
             float* __restrict__ C, const float* __restrict__ Cadd,
             const int* __restrict__ cnts, const int* __restrict__ asg_tok,
             const float* __restrict__ asg_w,
             const float* __restrict__ B2, float* __restrict__ C2,
             const float* __restrict__ Bsh, const float* __restrict__ Bsh2,
             int M, int N, int K)
{
    __shared__ uint32_t As[2][16][136];   // K-major: As[k][m]
    __shared__ uint32_t Bs[2][16][136];   // Bs[k][n]
    int e = 0;
    int Mloc = M;
    if (MODE >= 2) {
        int zz = blockIdx.z;
        int sel = 0;
        if (DUAL) { sel = zz & 1; zz >>= 1; }
        e = zz;
        Mloc = cnts[e];
        const float* Bdense = (DUAL && sel) ? B2 : B;
        const float* Bshared = (DUAL && sel) ? Bsh2 : Bsh;
        B = (e == NE) ? Bshared : Bdense + (size_t)e * K * N;
        if (DUAL && sel) C = C2;
    }
    int m0 = blockIdx.y * 128;
    int n0 = blockIdx.x * 128;
    if (m0 >= Mloc) return;

    const int tid = threadIdx.x;
    const int lane = tid & 31;
    const int warp = tid >> 5;           // 0..15
    const int gid = lane >> 2, tig = lane & 3;
    const int wm = (warp >> 2) * 32;     // 4 warp-rows
    const int wn = (warp & 3) * 32;      // 4 warp-cols

    // loaders: one float4 per thread for A and B
    const int arow = tid >> 2;           // 0..127
    const int ak = (tid & 3) << 2;       // 0,4,8,12
    const float* pa = nullptr;
    {
        int row = m0 + arow;
        if (row < Mloc) {
            int g = (MODE == 2) ? asg_tok[e * TCAP + row]
                  : ((MODE == 3) ? (e * TCAP + row) : row);
            pa = A + (size_t)g * K + ak;
        }
    }
    const int bk = tid >> 5;             // 0..15
    const int bn = (tid & 31) << 2;      // 0..124
    const float* pb = B + (size_t)bk * N + n0 + bn;

    float acc[2][4][4];
    #pragma unroll
    for (int mf = 0; mf < 2; mf++)
        #pragma unroll
        for (int nf = 0; nf < 4; nf++)
            #pragma unroll
            for (int r = 0; r < 4; r++) acc[mf][nf][r] = 0.f;

    float4 fa = pa ? *(const float4*)pa : make_float4(0.f, 0.f, 0.f, 0.f);
    float4 fb = *(const float4*)pb;

    for (int k0 = 0; k0 < K; k0 += 16) {
        int buf = (k0 >> 4) & 1;
        As[buf][ak + 0][arow] = f2tf(fa.x);
        As[buf][ak + 1][arow] = f2tf(fa.y);
        As[buf][ak + 2][arow] = f2tf(fa.z);
        As[buf][ak + 3][arow] = f2tf(fa.w);
        {
            uint4 bv;
            bv.x = f2tf(fb.x); bv.y = f2tf(fb.y);
            bv.z = f2tf(fb.z); bv.w = f2tf(fb.w);
            *(uint4*)&Bs[buf][bk][bn] = bv;
        }
        __syncthreads();
        if (k0 + 16 < K) {
            fa = pa ? *(const float4*)(pa + k0 + 16) : make_float4(0.f, 0.f, 0.f, 0.f);
            fb = *(const float4*)(pb + (size_t)(k0 + 16) * N);
        }
        // all fragment LDS issued as one independent batch, then 16 mmas
        uint32_t af[2][2][4], bf[2][4][2];
        #pragma unroll
        for (int ks = 0; ks < 2; ks++) {
            int k = ks * 8;
            #pragma unroll
            for (int mf = 0; mf < 2; mf++) {
                int mb = wm + mf * 16 + gid;
                af[ks][mf][0] = As[buf][k + tig][mb];
                af[ks][mf][1] = As[buf][k + tig][mb + 8];
                af[ks][mf][2] = As[buf][k + tig + 4][mb];
                af[ks][mf][3] = As[buf][k + tig + 4][mb + 8];
            }
            #pragma unroll
            for (int nf = 0; nf < 4; nf++) {
                int nb = wn + nf * 8 + gid;
                bf[ks][nf][0] = Bs[buf][k + tig][nb];
                bf[ks][nf][1] = Bs[buf][k + tig + 4][nb];
            }
        }
        #pragma unroll
        for (int ks = 0; ks < 2; ks++)
            #pragma unroll
            for (int mf = 0; mf < 2; mf++)
                #pragma unroll
                for (int nf = 0; nf < 4; nf++)
                    mma_tf32(acc[mf][nf], af[ks][mf], bf[ks][nf][0], bf[ks][nf][1]);
        // no second barrier: next STS targets the other buffer; frag LDS of this
        // iter precede it in program order, STS two iters out is fenced by the
        // next iteration's barrier.
    }

    #pragma unroll
    for (int mf = 0; mf < 2; mf++) {
        int r0 = m0 + wm + mf * 16 + gid;
        int r1 = r0 + 8;
        #pragma unroll
        for (int nf = 0; nf < 4; nf++) {
            int col = n0 + wn + nf * 8 + tig * 2;
            if (MODE == 3) {
                if (r0 < Mloc) {
                    int tok = asg_tok[e * TCAP + r0];
                    float w = asg_w[e * TCAP + r0];
                    float* cp = C + (size_t)tok * N + col;
                    atomicAdd(cp, w * acc[mf][nf][0]);
                    atomicAdd(cp + 1, w * acc[mf][nf][1]);
                }
                if (r1 < Mloc) {
                    int tok = asg_tok[e * TCAP + r1];
                    float w = asg_w[e * TCAP + r1];
                    float* cp = C + (size_t)tok * N + col;
                    atomicAdd(cp, w * acc[mf][nf][2]);
                    atomicAdd(cp + 1, w * acc[mf][nf][3]);
                }
            } else {
                if (r0 < Mloc) {
                    size_t cr = (MODE == 2) ? (size_t)(e * TCAP + r0) : (size_t)r0;
                    float2 v = make_float2(acc[mf][nf][0], acc[mf][nf][1]);
                    if (MODE == 1) {
                        float2 av = *(const float2*)(Cadd + (size_t)r0 * N + col);
                        v.x += av.x; v.y += av.y;
                    }
                    *(float2*)(C + cr * N + col) = v;
                }
                if (r1 < Mloc) {
                    size_t cr = (MODE == 2) ? (size_t)(e * TCAP + r1) : (size_t)r1;
                    float2 v = make_float2(acc[mf][nf][2], acc[mf][nf][3]);
                    if (MODE == 1) {
                        float2 av = *(const float2*)(Cadd + (size_t)r1 * N + col);
                        v.x += av.x; v.y += av.y;
                    }
                    *(float2*)(C + cr * N + col) = v;
                }
            }
        }
    }
}

// ---------------- RoPE (in-place on g_qkv) ----------------
__global__ void rope_kernel(const int* __restrict__ pos_ids)
{
    int t = blockIdx.x;
    float p = (float)pos_ids[t];
    const float c_l2 = -19.93156856932417f / 32.f;  // -log2(1e6)/32
    float* row = g_qkv + (size_t)t * QKV_N;
    for (int i = threadIdx.x; i < (NH + NKV) * 32; i += blockDim.x) {
        float* base;
        int d;
        if (i < NH * 32) {
            base = row + (size_t)(i >> 5) * HD;
            d = i & 31;
        } else {
            int j = i - NH * 32;
            base = row + 1024 + (size_t)(j >> 5) * HD;
            d = j & 31;
        }
        float f = p * exp2f((float)d * c_l2);
        float sn, cs;
        sincosf(f, &sn, &cs);
        float a = base[d], b2 = base[d + 32];
        base[d] = a * cs - b2 * sn;
        base[d + 32] = b2 * cs + a * sn;
    }
}

// ---------------- tensor-core flash attention (unchanged from R12) ----------------
#define ATR 72
#define ATT_SMEM ((128 * ATR + 64 * ATR) * 4)
__global__ __launch_bounds__(256)
void attn_tc_kernel()
{
    extern __shared__ uint32_t usm[];
    uint32_t* Qs = usm;
    uint32_t* Ks = usm + 128 * ATR;
    const int qb = gridDim.x - 1 - blockIdx.x;
    const int h = blockIdx.y, b = blockIdx.z;
    const int kvh = h >> 2;
    const int tid = threadIdx.x;
    const int lane = tid & 31, warp = tid >> 5;
    const int gid = lane >> 2, tig = lane & 3;
    const int m0 = warp * 16;

    for (int i = tid; i < 128 * 16; i += 256) {
        int row = i >> 4, c4 = (i & 15) << 2;
        float4 v = *(const float4*)(g_qkv + ((size_t)(b * S_LEN + qb * 128 + row)) * QKV_N + h * HD + c4);
        uint4 u;
        u.x = f2tf(v.x); u.y = f2tf(v.y); u.z = f2tf(v.z); u.w = f2tf(v.w);
        *(uint4*)(Qs + row * ATR + c4) = u;
    }
    __syncthreads();
    uint32_t qa[8][4];
    #pragma unroll
    for (int ks = 0; ks < 8; ks++) {
        int k = ks * 8;
        qa[ks][0] = Qs[(m0 + gid) * ATR + k + tig];
        qa[ks][1] = Qs[(m0 + gid + 8) * ATR + k + tig];
        qa[ks][2] = Qs[(m0 + gid) * ATR + k + tig + 4];
        qa[ks][3] = Qs[(m0 + gid + 8) * ATR + k + tig + 4];
    }
    __syncthreads();

    float mr0 = -1e30f, mr1 = -1e30f, l0 = 0.f, l1 = 0.f;
    float oacc[8][4];
    #pragma unroll
    for (int nf = 0; nf < 8; nf++)
        #pragma unroll
        for (int r = 0; r < 4; r++) oacc[nf][r] = 0.f;

    const int qrow0 = qb * 128 + m0 + gid;
    const int qrow1 = qrow0 + 8;
    const int ntile = 2 * qb + 2;

    for (int j = 0; j < ntile; j++) {
        for (int i = tid; i < 64 * 16; i += 256) {
            int row = i >> 4, c4 = (i & 15) << 2;
            float4 v = *(const float4*)(g_qkv + ((size_t)(b * S_LEN + j * 64 + row)) * QKV_N + 1024 + kvh * HD + c4);
            uint4 u;
            u.x = f2tf(v.x); u.y = f2tf(v.y); u.z = f2tf(v.z); u.w = f2tf(v.w);
            *(uint4*)(Ks + row * ATR + c4) = u;
        }
        __syncthreads();

        float s[8][4];
        #pragma unroll
        for (int nf = 0; nf < 8; nf++)
            #pragma unroll
            for (int r = 0; r < 4; r++) s[nf][r] = 0.f;
        #pragma unroll
        for (int ks = 0; ks < 8; ks++) {
            #pragma unroll
            for (int nf = 0; nf < 8; nf++) {
                uint32_t b0 = Ks[(nf * 8 + gid) * ATR + ks * 8 + tig];
                uint32_t b1 = Ks[(nf * 8 + gid) * ATR + ks * 8 + tig + 4];
                mma_tf32(s[nf], qa[ks], b0, b1);
            }
        }

        bool diag = (j >= 2 * qb);
        #pragma unroll
        for (int nf = 0; nf < 8; nf++) {
            int col = j * 64 + nf * 8 + tig * 2;
            s[nf][0] *= 0.125f; s[nf][1] *= 0.125f;
            s[nf][2] *= 0.125f; s[nf][3] *= 0.125f;
            if (diag) {
                if (col > qrow0)     s[nf][0] = -1e30f;
                if (col + 1 > qrow0) s[nf][1] = -1e30f;
                if (col > qrow1)     s[nf][2] = -1e30f;
                if (col + 1 > qrow1) s[nf][3] = -1e30f;
            }
        }

        float mx0 = -1e30f, mx1 = -1e30f;
        #pragma unroll
        for (int nf = 0; nf < 8; nf++) {
            mx0 = fmaxf(mx0, fmaxf(s[nf][0], s[nf][1]));
            mx1 = fmaxf(mx1, fmaxf(s[nf][2], s[nf][3]));
        }
        mx0 = fmaxf(mx0, __shfl_xor_sync(0xffffffffu, mx0, 1));
        mx0 = fmaxf(mx0, __shfl_xor_sync(0xffffffffu, mx0, 2));
        mx1 = fmaxf(mx1, __shfl_xor_sync(0xffffffffu, mx1, 1));
        mx1 = fmaxf(mx1, __shfl_xor_sync(0xffffffffu, mx1, 2));
        float mn0 = fmaxf(mr0, mx0), mn1 = fmaxf(mr1, mx1);
        float al0 = __expf(mr0 - mn0), al1 = __expf(mr1 - mn1);
        mr0 = mn0; mr1 = mn1;

        float ls0 = 0.f, ls1 = 0.f;
        #pragma unroll
        for (int nf = 0; nf < 8; nf++) {
            s[nf][0] = __expf(s[nf][0] - mn0);
            s[nf][1] = __expf(s[nf][1] - mn0);
            s[nf][2] = __expf(s[nf][2] - mn1);
            s[nf][3] = __expf(s[nf][3] - mn1);
            ls0 += s[nf][0] + s[nf][1];
            ls1 += s[nf][2] + s[nf][3];
        }
        ls0 += __shfl_xor_sync(0xffffffffu, ls0, 1);
        ls0 += __shfl_xor_sync(0xffffffffu, ls0, 2);
        ls1 += __shfl_xor_sync(0xffffffffu, ls1, 1);
        ls1 += __shfl_xor_sync(0xffffffffu, ls1, 2);
        l0 = l0 * al0 + ls0;
        l1 = l1 * al1 + ls1;
        #pragma unroll
        for (int nf = 0; nf < 8; nf++) {
            oacc[nf][0] *= al0; oacc[nf][1] *= al0;
            oacc[nf][2] *= al1; oacc[nf][3] *= al1;
        }

        #pragma unroll
        for (int nf = 0; nf < 8; nf++) {
            int cl = nf * 8 + tig * 2;
            uint2 p01 = make_uint2(f2tf(s[nf][0]), f2tf(s[nf][1]));
            uint2 p23 = make_uint2(f2tf(s[nf][2]), f2tf(s[nf][3]));
            *(uint2*)(Qs + (m0 + gid) * ATR + cl) = p01;
            *(uint2*)(Qs + (m0 + gid + 8) * ATR + cl) = p23;
        }
        __syncthreads();

        for (int i = tid; i < 64 * 16; i += 256) {
            int row = i >> 4, c4 = (i & 15) << 2;
            float4 v = *(const float4*)(g_qkv + ((size_t)(b * S_LEN + j * 64 + row)) * QKV_N + 1280 + kvh * HD + c4);
            uint4 u;
            u.x = f2tf(v.x); u.y = f2tf(v.y); u.z = f2tf(v.z); u.w = f2tf(v.w);
            *(uint4*)(Ks + row * ATR + c4) = u;
        }
        __syncthreads();

        #pragma unroll
        for (int ks = 0; ks < 8; ks++) {
            uint32_t pa[4];
            pa[0] = Qs[(m0 + gid) * ATR + ks * 8 + tig];
            pa[1] = Qs[(m0 + gid + 8) * ATR + ks * 8 + tig];
            pa[2] = Qs[(m0 + gid) * ATR + ks * 8 + tig + 4];
            pa[3] = Qs[(m0 + gid + 8) * ATR + ks * 8 + tig + 4];
            #pragma unroll
            for (int nf = 0; nf < 8; nf++) {
                uint32_t b0 = Ks[(ks * 8 + tig) * ATR + nf * 8 + gid];
                uint32_t b1 = Ks[(ks * 8 + tig + 4) * ATR + nf * 8 + gid];
                mma_tf32(oacc[nf], pa, b0, b1);
            }
        }
        __syncthreads();
    }

    float inv0 = 1.f / l0, inv1 = 1.f / l1;
    #pragma unroll
    for (int nf = 0; nf < 8; nf++) {
        int col = h * HD + nf * 8 + tig * 2;
        float2 o0 = make_float2(oacc[nf][0] * inv0, oacc[nf][1] * inv0);
        float2 o1 = make_float2(oacc[nf][2] * inv1, oacc[nf][3] * inv1);
        *(float2*)(g_attn + ((size_t)(b * S_LEN + qrow0)) * (NH * HD) + col) = o0;
        *(float2*)(g_attn + ((size_t)(b * S_LEN + qrow1)) * (NH * HD) + col) = o1;
    }
}

// ---------------- router: softmax + top2 + assignment lists ----------------
__global__ void router_kernel(const float* __restrict__ rw)
{
    int warp = threadIdx.x >> 5, lane = threadIdx.x & 31;
    int t = blockIdx.x * 8 + warp;
    const float* xr = g_x2 + (size_t)t * H_DIM;
    float a[8];
    #pragma unroll
    for (int i = 0; i < 8; i++) a[i] = 0.f;
    for (int k = lane; k < H_DIM; k += 32) {
        float xv = xr[k];
        const float4* wp = (const float4*)(rw + (size_t)k * 8);
        float4 w0 = wp[0], w1 = wp[1];
        a[0] += xv * w0.x; a[1] += xv * w0.y; a[2] += xv * w0.z; a[3] += xv * w0.w;
        a[4] += xv * w1.x; a[5] += xv * w1.y; a[6] += xv * w1.z; a[7] += xv * w1.w;
    }
    #pragma unroll
    for (int off = 16; off; off >>= 1)
        #pragma unroll
        for (int i = 0; i < 8; i++) a[i] += __shfl_xor_sync(0xffffffffu, a[i], off);
    if (lane == 0) {
        float mx = a[0];
        #pragma unroll
        for (int i = 1; i < 8; i++) mx = fmaxf(mx, a[i]);
        float p[8], sum = 0.f;
        #pragma unroll
        for (int i = 0; i < 8; i++) { p[i] = expf(a[i] - mx); sum += p[i]; }
        float inv = 1.f / sum;
        #pragma unroll
        for (int i = 0; i < 8; i++) { p[i] *= inv; g_probs[t * 8 + i] = p[i]; }
        int i1 = 0; float v1 = p[0];
        #pragma unroll
        for (int i = 1; i < 8; i++) if (p[i] > v1) { v1 = p[i]; i1 = i; }
        int i2 = -1; float v2 = -1.f;
        #pragma unroll
        for (int i = 0; i < 8; i++) if (i != i1 && p[i] > v2) { v2 = p[i]; i2 = i; }
        int s1 = atomicAdd(&g_cnt[i1], 1);
        g_asg_tok[i1 * TCAP + s1] = t; g_asg_w[i1 * TCAP + s1] = v1;
        int s2 = atomicAdd(&g_cnt[i2], 1);
        g_asg_tok[i2 * TCAP + s2] = t; g_asg_w[i2 * TCAP + s2] = v2;
    }
}

// ---------------- silu(G)*U in place (G), float4; covers experts 0..NE ----------------
__global__ void silumul_kernel()
{
    int e = blockIdx.y;
    int row = blockIdx.x;
    if (row >= g_cnt[e]) return;
    float4* gp = (float4*)(g_G + ((size_t)e * TCAP + row) * I_DIM);
    const float4* up = (const float4*)(g_U + ((size_t)e * TCAP + row) * I_DIM);
    int i = threadIdx.x;
    float4 g = gp[i];
    float4 u = up[i];
    g.x = (g.x / (1.f + __expf(-g.x))) * u.x;
    g.y = (g.y / (1.f + __expf(-g.y))) * u.y;
    g.z = (g.z / (1.f + __expf(-g.z))) * u.z;
    g.w = (g.w / (1.f + __expf(-g.w))) * u.w;
    gp[i] = g;
}

// ---------------- shared-expert sigmoid gate -> asg_w[NE] ----------------
__global__ void sgate_kernel(const float* __restrict__ segw)
{
    int warp = threadIdx.x >> 5, lane = threadIdx.x & 31;
    int t = blockIdx.x * 8 + warp;
    const float* xr = g_x2 + (size_t)t * H_DIM;
    float a = 0.f;
    for (int k = lane; k < H_DIM; k += 32) a += xr[k] * segw[k];
    #pragma unroll
    for (int off = 16; off; off >>= 1) a += __shfl_xor_sync(0xffffffffu, a, off);
    if (lane == 0) g_asg_w[NE * TCAP + t] = 1.f / (1.f + expf(-a));
}

// ---------------- final combine: out = resid + moe (moe includes gated shared) --------
__global__ void combine_kernel(float* __restrict__ out)
{
    int i = blockIdx.x * blockDim.x + threadIdx.x;
    if (i < T_TOK * H_DIM)
        out[i] = g_resid[i] + g_moe[i];
}

// ---------------- aux loss ----------------
__global__ void aux_kernel(float* __restrict__ out_aux)
{
    __shared__ float sm[256];
    int tid = threadIdx.x;
    int e = tid & 7;
    int chunk = tid >> 3;
    float s = 0.f;
    for (int t = chunk; t < T_TOK; t += 32) s += g_probs[t * 8 + e];
    sm[tid] = s;
    __syncthreads();
    for (int st = 16; st >= 1; st >>= 1) {
        if (chunk < st) sm[tid] += sm[tid + st * 8];
        __syncthreads();
    }
    if (tid == 0) {
        float aux = 0.f;
        #pragma unroll
        for (int i = 0; i < 8; i++) {
            float m = sm[i] / (float)T_TOK - 0.125f;
            aux += m * m;
        }
        out_aux[0] = aux / 8.f;
    }
}

// ---------------- launch ----------------
extern "C" void kernel_launch(void* const* d_in, const int* in_sizes, int n_in,
                              void* d_out, int out_size)
{
    const float* hidden = (const float*)d_in[0];
    const int*   pos    = (const int*)d_in[2];
    const float* ln1    = (const float*)d_in[3];
    const float* ln2    = (const float*)d_in[4];
    const float* wq     = (const float*)d_in[5];
    const float* wk     = (const float*)d_in[6];
    const float* wv     = (const float*)d_in[7];
    const float* wo     = (const float*)d_in[8];
    const float* rw     = (const float*)d_in[9];
    const float* egw    = (const float*)d_in[10];
    const float* euw    = (const float*)d_in[11];
    const float* edw    = (const float*)d_in[12];
    const float* sgw    = (const float*)d_in[13];
    const float* suw    = (const float*)d_in[14];
    const float* sdw    = (const float*)d_in[15];
    const float* segw   = (const float*)d_in[16];
    float* out = (float*)d_out;

    float *x1, *qkv, *attn, *resid, *x2, *moe, *G, *U, *asw, *wqkv;
    int *cnt, *ast;
    cudaGetSymbolAddress((void**)&x1, g_x1);
    cudaGetSymbolAddress((void**)&qkv, g_qkv);
    cudaGetSymbolAddress((void**)&attn, g_attn);
    cudaGetSymbolAddress((void**)&resid, g_resid);
    cudaGetSymbolAddress((void**)&x2, g_x2);
    cudaGetSymbolAddress((void**)&moe, g_moe);
    cudaGetSymbolAddress((void**)&G, g_G);
    cudaGetSymbolAddress((void**)&U, g_U);
    cudaGetSymbolAddress((void**)&cnt, g_cnt);
    cudaGetSymbolAddress((void**)&ast, g_asg_tok);
    cudaGetSymbolAddress((void**)&asw, g_asg_w);
    cudaGetSymbolAddress((void**)&wqkv, g_wqkv);

    cudaFuncSetAttribute((const void*)attn_tc_kernel,
                         cudaFuncAttributeMaxDynamicSharedMemorySize, ATT_SMEM);

    zero_kernel<<<(T_TOK * H_DIM + 255) / 256, 256>>>();
    concat_qkv_w<<<(H_DIM * QKV_N + 255) / 256, 256>>>(wq, wk, wv);

    // attention block
    rmsnorm_kernel<<<T_TOK, 256>>>(hidden, ln1, x1);
    gemm_tc<0, 0><<<dim3(12, 16), 512>>>(x1, wqkv, qkv, nullptr, nullptr, nullptr, nullptr,
                                         nullptr, nullptr, nullptr, nullptr, T_TOK, QKV_N, 1024);
    rope_kernel<<<T_TOK, 256>>>(pos);
    attn_tc_kernel<<<dim3(8, NH, B_SZ), 256, ATT_SMEM>>>();
    gemm_tc<1, 0><<<dim3(8, 16), 512>>>(attn, wo, resid, hidden, nullptr, nullptr, nullptr,
                                        nullptr, nullptr, nullptr, nullptr, T_TOK, 1024, 1024);

    // MoE block (shared expert folded in as expert NE)
    rmsnorm_kernel<<<T_TOK, 256>>>(resid, ln2, x2);
    router_kernel<<<T_TOK / 8, 256>>>(rw);
    sgate_kernel<<<T_TOK / 8, 256>>>(segw);
    gemm_tc<2, 1><<<dim3(8, 16, (NE + 1) * 2), 512>>>(x2, egw, G, nullptr, cnt, ast, nullptr,
                                                      euw, U, sgw, suw, TCAP, 1024, 1024);
    silumul_kernel<<<dim3(TCAP, NE + 1), 256>>>();
    gemm_tc<3, 0><<<dim3(8, 16, NE + 1), 512>>>(G, edw, moe, nullptr, cnt, ast, asw,
                                                nullptr, nullptr, sdw, nullptr, TCAP, 1024, 1024);

    combine_kernel<<<(T_TOK * H_DIM + 255) / 256, 256>>>(out);
    if (out_size > T_TOK * H_DIM)
        aux_kernel<<<1, 256>>>(out + (out_size - 1));
}

// round 15
// speedup vs baseline: 1.1002x; 1.1002x over previous
#include <cuda_runtime.h>
#include <cuda_bf16.h>
#include <math.h>
#include <stdint.h>

#define T_TOK 2048
#define H_DIM 1024
#define I_DIM 1024
#define S_LEN 1024
#define B_SZ  2
#define NH    16
#define NKV   4
#define HD    64
#define NE    8
#define TCAP  2048
#define QKV_N 1536   // 1024 q + 256 k + 256 v

// ---------------- scratch ----------------
__device__ float g_x1[T_TOK * H_DIM];
__device__ float g_qkv[T_TOK * QKV_N];
__device__ float g_attn[T_TOK * NH * HD];
__device__ float g_resid[T_TOK * H_DIM];
__device__ float g_x2[T_TOK * H_DIM];
__device__ float g_moe[T_TOK * H_DIM];
__device__ float g_G[(NE + 1) * TCAP * I_DIM];   // expert 8 = shared expert
__device__ float g_U[(NE + 1) * TCAP * I_DIM];
__device__ float g_wqkv[H_DIM * QKV_N];
__device__ float g_probs[T_TOK * NE];
__device__ int   g_cnt[NE + 1];
__device__ int   g_asg_tok[(NE + 1) * TCAP];
__device__ float g_asg_w[(NE + 1) * TCAP];

// raw fp32 bits fed to tf32 mma: HW uses the top mantissa bits (truncation).
__device__ __forceinline__ uint32_t f2u(float x) { return __float_as_uint(x); }

__device__ __forceinline__ void mma_tf32(float* c, const uint32_t* a, uint32_t b0, uint32_t b1)
{
    asm volatile(
        "mma.sync.aligned.m16n8k8.row.col.f32.tf32.tf32.f32 "
        "{%0,%1,%2,%3},{%4,%5,%6,%7},{%8,%9},{%0,%1,%2,%3};"
        : "+f"(c[0]), "+f"(c[1]), "+f"(c[2]), "+f"(c[3])
        : "r"(a[0]), "r"(a[1]), "r"(a[2]), "r"(a[3]), "r"(b0), "r"(b1));
}

// ---------------- zero + expert-8 identity assignment (inside graph) ----------------
__global__ void zero_kernel()
{
    int i = blockIdx.x * blockDim.x + threadIdx.x;
    if (i < T_TOK * H_DIM) g_moe[i] = 0.f;
    if (i < NE) g_cnt[i] = 0;
    if (i == NE) g_cnt[NE] = TCAP;
    if (i < TCAP) g_asg_tok[NE * TCAP + i] = i;
}

// ---------------- concat wq|wk|wv -> g_wqkv [H][1536] ----------------
__global__ void concat_qkv_w(const float* __restrict__ wq, const float* __restrict__ wk,
                             const float* __restrict__ wv)
{
    int idx = blockIdx.x * blockDim.x + threadIdx.x;
    if (idx >= H_DIM * QKV_N) return;
    int r = idx / QKV_N, c = idx - r * QKV_N;
    float v;
    if (c < 1024)      v = wq[r * 1024 + c];
    else if (c < 1280) v = wk[r * 256 + (c - 1024)];
    else               v = wv[r * 256 + (c - 1280)];
    g_wqkv[idx] = v;
}

// ---------------- RMSNorm ----------------
__global__ void rmsnorm_kernel(const float* __restrict__ x, const float* __restrict__ w,
                               float* __restrict__ y)
{
    __shared__ float red[8];
    __shared__ float s_inv;
    int t = blockIdx.x;
    int tid = threadIdx.x;
    const float4* xp = (const float4*)(x + (size_t)t * H_DIM);
    float4 v = xp[tid];
    float ss = v.x * v.x + v.y * v.y + v.z * v.z + v.w * v.w;
    #pragma unroll
    for (int off = 16; off; off >>= 1) ss += __shfl_xor_sync(0xffffffffu, ss, off);
    if ((tid & 31) == 0) red[tid >> 5] = ss;
    __syncthreads();
    if (tid == 0) {
        float s = 0.f;
        #pragma unroll
        for (int i = 0; i < 8; i++) s += red[i];
        s_inv = rsqrtf(s / (float)H_DIM + 1e-6f);
    }
    __syncthreads();
    float inv = s_inv;
    const float4* wp = (const float4*)w;
    float4 wv = wp[tid];
    float4 o;
    o.x = v.x * inv * wv.x; o.y = v.y * inv * wv.y;
    o.z = v.z * inv * wv.z; o.w = v.w * inv * wv.w;
    ((float4*)(y + (size_t)t * H_DIM))[tid] = o;
}

// ---------------- tf32 TC GEMM: 128x128x16, 256 thr, 64x32 warp tile (R12 shape) -------
// MODE 0: C = A@B            MODE 1: C = Cadd + A@B
// MODE 2: per-expert gather rows of A via asg_tok; C row = e*TCAP + local
//         (e == NE -> shared expert, B = Bsh)
// MODE 3: per-expert A row = e*TCAP+local; atomicAdd C[tok] * asg_w  (e==NE -> Bsh)
// DUAL 1 (with MODE 2): blockIdx.z LSB selects (B,C,Bsh) vs (B2,C2,Bsh2)
template<int MODE, int DUAL>
__global__ __launch_bounds__(256)
void gemm_tc(const float* __restrict__ A, const float* __restrict__ B,
             float* __restrict__ C, const float* __restrict__ Cadd,
             const int* __restrict__ cnts, const int* __restrict__ asg_tok,
             const float* __restrict__ asg_w,
             const float* __restrict__ B2, float* __restrict__ C2,
             const float* __restrict__ Bsh, const float* __restrict__ Bsh2,
             int M, int N, int K)
{
    __shared__ uint32_t As[2][16][136];   // K-major: As[k][m]
    __shared__ uint32_t Bs[2][16][136];   // Bs[k][n]
    int e = 0;
    int Mloc = M;
    if (MODE >= 2) {
        int zz = blockIdx.z;
        int sel = 0;
        if (DUAL) { sel = zz & 1; zz >>= 1; }
        e = zz;
        Mloc = cnts[e];
        const float* Bdense = (DUAL && sel) ? B2 : B;
        const float* Bshared = (DUAL && sel) ? Bsh2 : Bsh;
        B = (e == NE) ? Bshared : Bdense + (size_t)e * K * N;
        if (DUAL && sel) C = C2;
    }
    int m0 = blockIdx.y * 128;
    int n0 = blockIdx.x * 128;
    if (m0 >= Mloc) return;

    const int tid = threadIdx.x;
    const int lane = tid & 31;
    const int warp = tid >> 5;
    const int gid = lane >> 2, tig = lane & 3;
    const int wm = (warp >> 2) * 64;
    const int wn = (warp & 3) * 32;

    int a_am[2], a_ak[2];
    const float* a_p[2];
    #pragma unroll
    for (int i = 0; i < 2; i++) {
        int idx = tid + i * 256;
        a_am[i] = idx >> 2;
        a_ak[i] = (idx & 3) << 2;
        int row = m0 + a_am[i];
        a_p[i] = nullptr;
        if (row < Mloc) {
            int g = (MODE == 2) ? asg_tok[e * TCAP + row]
                  : ((MODE == 3) ? (e * TCAP + row) : row);
            a_p[i] = A + (size_t)g * K + a_ak[i];
        }
    }
    int b_bk[2], b_bn[2];
    const float* b_p[2];
    #pragma unroll
    for (int i = 0; i < 2; i++) {
        int idx = tid + i * 256;
        b_bk[i] = idx >> 5;
        b_bn[i] = (idx & 31) << 2;
        b_p[i] = B + (size_t)b_bk[i] * N + n0 + b_bn[i];
    }

    float acc[4][4][4];
    #pragma unroll
    for (int mf = 0; mf < 4; mf++)
        #pragma unroll
        for (int nf = 0; nf < 4; nf++)
            #pragma unroll
            for (int r = 0; r < 4; r++) acc[mf][nf][r] = 0.f;

    float4 fa[2], fb[2];
    #pragma unroll
    for (int i = 0; i < 2; i++) {
        fa[i] = a_p[i] ? *(const float4*)(a_p[i]) : make_float4(0.f, 0.f, 0.f, 0.f);
        fb[i] = *(const float4*)(b_p[i]);
    }

    for (int k0 = 0; k0 < K; k0 += 16) {
        int buf = (k0 >> 4) & 1;
        #pragma unroll
        for (int i = 0; i < 2; i++) {
            As[buf][a_ak[i] + 0][a_am[i]] = f2u(fa[i].x);
            As[buf][a_ak[i] + 1][a_am[i]] = f2u(fa[i].y);
            As[buf][a_ak[i] + 2][a_am[i]] = f2u(fa[i].z);
            As[buf][a_ak[i] + 3][a_am[i]] = f2u(fa[i].w);
            uint4 bv;
            bv.x = f2u(fb[i].x); bv.y = f2u(fb[i].y);
            bv.z = f2u(fb[i].z); bv.w = f2u(fb[i].w);
            *(uint4*)&Bs[buf][b_bk[i]][b_bn[i]] = bv;
        }
        __syncthreads();
        if (k0 + 16 < K) {
            #pragma unroll
            for (int i = 0; i < 2; i++) {
                fa[i] = a_p[i] ? *(const float4*)(a_p[i] + k0 + 16)
                               : make_float4(0.f, 0.f, 0.f, 0.f);
                fb[i] = *(const float4*)(b_p[i] + (size_t)(k0 + 16) * N);
            }
        }
        #pragma unroll
        for (int ks = 0; ks < 16; ks += 8) {
            uint32_t af[4][4], bf[4][2];
            #pragma unroll
            for (int mf = 0; mf < 4; mf++) {
                int mb = wm + mf * 16 + gid;
                af[mf][0] = As[buf][ks + tig][mb];
                af[mf][1] = As[buf][ks + tig][mb + 8];
                af[mf][2] = As[buf][ks + tig + 4][mb];
                af[mf][3] = As[buf][ks + tig + 4][mb + 8];
            }
            #pragma unroll
            for (int nf = 0; nf < 4; nf++) {
                int nb = wn + nf * 8 + gid;
                bf[nf][0] = Bs[buf][ks + tig][nb];
                bf[nf][1] = Bs[buf][ks + tig + 4][nb];
            }
            #pragma unroll
            for (int mf = 0; mf < 4; mf++)
                #pragma unroll
                for (int nf = 0; nf < 4; nf++)
                    mma_tf32(acc[mf][nf], af[mf], bf[nf][0], bf[nf][1]);
        }
        __syncthreads();
    }

    #pragma unroll
    for (int mf = 0; mf < 4; mf++) {
        int r0 = m0 + wm + mf * 16 + gid;
        int r1 = r0 + 8;
        #pragma unroll
        for (int nf = 0; nf < 4; nf++) {
            int col = n0 + wn + nf * 8 + tig * 2;
            if (MODE == 3) {
                if (r0 < Mloc) {
                    int tok = asg_tok[e * TCAP + r0];
                    float w = asg_w[e * TCAP + r0];
                    float* cp = C + (size_t)tok * N + col;
                    atomicAdd(cp, w * acc[mf][nf][0]);
                    atomicAdd(cp + 1, w * acc[mf][nf][1]);
                }
                if (r1 < Mloc) {
                    int tok = asg_tok[e * TCAP + r1];
                    float w = asg_w[e * TCAP + r1];
                    float* cp = C + (size_t)tok * N + col;
                    atomicAdd(cp, w * acc[mf][nf][2]);
                    atomicAdd(cp + 1, w * acc[mf][nf][3]);
                }
            } else {
                if (r0 < Mloc) {
                    size_t cr = (MODE == 2) ? (size_t)(e * TCAP + r0) : (size_t)r0;
                    float2 v = make_float2(acc[mf][nf][0], acc[mf][nf][1]);
                    if (MODE == 1) {
                        float2 av = *(const float2*)(Cadd + (size_t)r0 * N + col);
                        v.x += av.x; v.y += av.y;
                    }
                    *(float2*)(C + cr * N + col) = v;
                }
                if (r1 < Mloc) {
                    size_t cr = (MODE == 2) ? (size_t)(e * TCAP + r1) : (size_t)r1;
                    float2 v = make_float2(acc[mf][nf][2], acc[mf][nf][3]);
                    if (MODE == 1) {
                        float2 av = *(const float2*)(Cadd + (size_t)r1 * N + col);
                        v.x += av.x; v.y += av.y;
                    }
                    *(float2*)(C + cr * N + col) = v;
                }
            }
        }
    }
}

// ---------------- RoPE (in-place on g_qkv) ----------------
__global__ void rope_kernel(const int* __restrict__ pos_ids)
{
    int t = blockIdx.x;
    float p = (float)pos_ids[t];
    const float c_l2 = -19.93156856932417f / 32.f;  // -log2(1e6)/32
    float* row = g_qkv + (size_t)t * QKV_N;
    for (int i = threadIdx.x; i < (NH + NKV) * 32; i += blockDim.x) {
        float* base;
        int d;
        if (i < NH * 32) {
            base = row + (size_t)(i >> 5) * HD;
            d = i & 31;
        } else {
            int j = i - NH * 32;
            base = row + 1024 + (size_t)(j >> 5) * HD;
            d = j & 31;
        }
        float f = p * exp2f((float)d * c_l2);
        float sn, cs;
        sincosf(f, &sn, &cs);
        float a = base[d], b2 = base[d + 32];
        base[d] = a * cs - b2 * sn;
        base[d + 32] = b2 * cs + a * sn;
    }
}

// ---------------- tensor-core flash attention (R12 structure, raw fp32 bits) ----------
#define ATR 72
#define ATT_SMEM ((128 * ATR + 64 * ATR) * 4)
__global__ __launch_bounds__(256)
void attn_tc_kernel()
{
    extern __shared__ uint32_t usm[];
    uint32_t* Qs = usm;
    uint32_t* Ks = usm + 128 * ATR;
    const int qb = gridDim.x - 1 - blockIdx.x;
    const int h = blockIdx.y, b = blockIdx.z;
    const int kvh = h >> 2;
    const int tid = threadIdx.x;
    const int lane = tid & 31, warp = tid >> 5;
    const int gid = lane >> 2, tig = lane & 3;
    const int m0 = warp * 16;

    for (int i = tid; i < 128 * 16; i += 256) {
        int row = i >> 4, c4 = (i & 15) << 2;
        *(uint4*)(Qs + row * ATR + c4) =
            *(const uint4*)(g_qkv + ((size_t)(b * S_LEN + qb * 128 + row)) * QKV_N + h * HD + c4);
    }
    __syncthreads();
    uint32_t qa[8][4];
    #pragma unroll
    for (int ks = 0; ks < 8; ks++) {
        int k = ks * 8;
        qa[ks][0] = Qs[(m0 + gid) * ATR + k + tig];
        qa[ks][1] = Qs[(m0 + gid + 8) * ATR + k + tig];
        qa[ks][2] = Qs[(m0 + gid) * ATR + k + tig + 4];
        qa[ks][3] = Qs[(m0 + gid + 8) * ATR + k + tig + 4];
    }
    __syncthreads();

    float mr0 = -1e30f, mr1 = -1e30f, l0 = 0.f, l1 = 0.f;
    float oacc[8][4];
    #pragma unroll
    for (int nf = 0; nf < 8; nf++)
        #pragma unroll
        for (int r = 0; r < 4; r++) oacc[nf][r] = 0.f;

    const int qrow0 = qb * 128 + m0 + gid;
    const int qrow1 = qrow0 + 8;
    const int ntile = 2 * qb + 2;

    for (int j = 0; j < ntile; j++) {
        for (int i = tid; i < 64 * 16; i += 256) {
            int row = i >> 4, c4 = (i & 15) << 2;
            *(uint4*)(Ks + row * ATR + c4) =
                *(const uint4*)(g_qkv + ((size_t)(b * S_LEN + j * 64 + row)) * QKV_N + 1024 + kvh * HD + c4);
        }
        __syncthreads();

        float s[8][4];
        #pragma unroll
        for (int nf = 0; nf < 8; nf++)
            #pragma unroll
            for (int r = 0; r < 4; r++) s[nf][r] = 0.f;
        #pragma unroll
        for (int ks = 0; ks < 8; ks++) {
            #pragma unroll
            for (int nf = 0; nf < 8; nf++) {
                uint32_t b0 = Ks[(nf * 8 + gid) * ATR + ks * 8 + tig];
                uint32_t b1 = Ks[(nf * 8 + gid) * ATR + ks * 8 + tig + 4];
                mma_tf32(s[nf], qa[ks], b0, b1);
            }
        }

        bool diag = (j >= 2 * qb);
        #pragma unroll
        for (int nf = 0; nf < 8; nf++) {
            int col = j * 64 + nf * 8 + tig * 2;
            s[nf][0] *= 0.125f; s[nf][1] *= 0.125f;
            s[nf][2] *= 0.125f; s[nf][3] *= 0.125f;
            if (diag) {
                if (col > qrow0)     s[nf][0] = -1e30f;
                if (col + 1 > qrow0) s[nf][1] = -1e30f;
                if (col > qrow1)     s[nf][2] = -1e30f;
                if (col + 1 > qrow1) s[nf][3] = -1e30f;
            }
        }

        float mx0 = -1e30f, mx1 = -1e30f;
        #pragma unroll
        for (int nf = 0; nf < 8; nf++) {
            mx0 = fmaxf(mx0, fmaxf(s[nf][0], s[nf][1]));
            mx1 = fmaxf(mx1, fmaxf(s[nf][2], s[nf][3]));
        }
        mx0 = fmaxf(mx0, __shfl_xor_sync(0xffffffffu, mx0, 1));
        mx0 = fmaxf(mx0, __shfl_xor_sync(0xffffffffu, mx0, 2));
        mx1 = fmaxf(mx1, __shfl_xor_sync(0xffffffffu, mx1, 1));
        mx1 = fmaxf(mx1, __shfl_xor_sync(0xffffffffu, mx1, 2));
        float mn0 = fmaxf(mr0, mx0), mn1 = fmaxf(mr1, mx1);
        float al0 = __expf(mr0 - mn0), al1 = __expf(mr1 - mn1);
        mr0 = mn0; mr1 = mn1;

        float ls0 = 0.f, ls1 = 0.f;
        #pragma unroll
        for (int nf = 0; nf < 8; nf++) {
            s[nf][0] = __expf(s[nf][0] - mn0);
            s[nf][1] = __expf(s[nf][1] - mn0);
            s[nf][2] = __expf(s[nf][2] - mn1);
            s[nf][3] = __expf(s[nf][3] - mn1);
            ls0 += s[nf][0] + s[nf][1];
            ls1 += s[nf][2] + s[nf][3];
        }
        ls0 += __shfl_xor_sync(0xffffffffu, ls0, 1);
        ls0 += __shfl_xor_sync(0xffffffffu, ls0, 2);
        ls1 += __shfl_xor_sync(0xffffffffu, ls1, 1);
        ls1 += __shfl_xor_sync(0xffffffffu, ls1, 2);
        l0 = l0 * al0 + ls0;
        l1 = l1 * al1 + ls1;
        #pragma unroll
        for (int nf = 0; nf < 8; nf++) {
            oacc[nf][0] *= al0; oacc[nf][1] *= al0;
            oacc[nf][2] *= al1; oacc[nf][3] *= al1;
        }

        #pragma unroll
        for (int nf = 0; nf < 8; nf++) {
            int cl = nf * 8 + tig * 2;
            uint2 p01 = make_uint2(f2u(s[nf][0]), f2u(s[nf][1]));
            uint2 p23 = make_uint2(f2u(s[nf][2]), f2u(s[nf][3]));
            *(uint2*)(Qs + (m0 + gid) * ATR + cl) = p01;
            *(uint2*)(Qs + (m0 + gid + 8) * ATR + cl) = p23;
        }
        __syncthreads();

        for (int i = tid; i < 64 * 16; i += 256) {
            int row = i >> 4, c4 = (i & 15) << 2;
            *(uint4*)(Ks + row * ATR + c4) =
                *(const uint4*)(g_qkv + ((size_t)(b * S_LEN + j * 64 + row)) * QKV_N + 1280 + kvh * HD + c4);
        }
        __syncthreads();

        #pragma unroll
        for (int ks = 0; ks < 8; ks++) {
            uint32_t pa[4];
            pa[0] = Qs[(m0 + gid) * ATR + ks * 8 + tig];
            pa[1] = Qs[(m0 + gid + 8) * ATR + ks * 8 + tig];
            pa[2] = Qs[(m0 + gid) * ATR + ks * 8 + tig + 4];
            pa[3] = Qs[(m0 + gid + 8) * ATR + ks * 8 + tig + 4];
            #pragma unroll
            for (int nf = 0; nf < 8; nf++) {
                uint32_t b0 = Ks[(ks * 8 + tig) * ATR + nf * 8 + gid];
                uint32_t b1 = Ks[(ks * 8 + tig + 4) * ATR + nf * 8 + gid];
                mma_tf32(oacc[nf], pa, b0, b1);
            }
        }
        __syncthreads();
    }

    float inv0 = 1.f / l0, inv1 = 1.f / l1;
    #pragma unroll
    for (int nf = 0; nf < 8; nf++) {
        int col = h * HD + nf * 8 + tig * 2;
        float2 o0 = make_float2(oacc[nf][0] * inv0, oacc[nf][1] * inv0);
        float2 o1 = make_float2(oacc[nf][2] * inv1, oacc[nf][3] * inv1);
        *(float2*)(g_attn + ((size_t)(b * S_LEN + qrow0)) * (NH * HD) + col) = o0;
        *(float2*)(g_attn + ((size_t)(b * S_LEN + qrow1)) * (NH * HD) + col) = o1;
    }
}

// ---------------- router: softmax + top2 + assignment lists ----------------
__global__ void router_kernel(const float* __restrict__ rw)
{
    int warp = threadIdx.x >> 5, lane = threadIdx.x & 31;
    int t = blockIdx.x * 8 + warp;
    const float* xr = g_x2 + (size_t)t * H_DIM;
    float a[8];
    #pragma unroll
    for (int i = 0; i < 8; i++) a[i] = 0.f;
    for (int k = lane; k < H_DIM; k += 32) {
        float xv = xr[k];
        const float4* wp = (const float4*)(rw + (size_t)k * 8);
        float4 w0 = wp[0], w1 = wp[1];
        a[0] += xv * w0.x; a[1] += xv * w0.y; a[2] += xv * w0.z; a[3] += xv * w0.w;
        a[4] += xv * w1.x; a[5] += xv * w1.y; a[6] += xv * w1.z; a[7] += xv * w1.w;
    }
    #pragma unroll
    for (int off = 16; off; off >>= 1)
        #pragma unroll
        for (int i = 0; i < 8; i++) a[i] += __shfl_xor_sync(0xffffffffu, a[i], off);
    if (lane == 0) {
        float mx = a[0];
        #pragma unroll
        for (int i = 1; i < 8; i++) mx = fmaxf(mx, a[i]);
        float p[8], sum = 0.f;
        #pragma unroll
        for (int i = 0; i < 8; i++) { p[i] = expf(a[i] - mx); sum += p[i]; }
        float inv = 1.f / sum;
        #pragma unroll
        for (int i = 0; i < 8; i++) { p[i] *= inv; g_probs[t * 8 + i] = p[i]; }
        int i1 = 0; float v1 = p[0];
        #pragma unroll
        for (int i = 1; i < 8; i++) if (p[i] > v1) { v1 = p[i]; i1 = i; }
        int i2 = -1; float v2 = -1.f;
        #pragma unroll
        for (int i = 0; i < 8; i++) if (i != i1 && p[i] > v2) { v2 = p[i]; i2 = i; }
        int s1 = atomicAdd(&g_cnt[i1], 1);
        g_asg_tok[i1 * TCAP + s1] = t; g_asg_w[i1 * TCAP + s1] = v1;
        int s2 = atomicAdd(&g_cnt[i2], 1);
        g_asg_tok[i2 * TCAP + s2] = t; g_asg_w[i2 * TCAP + s2] = v2;
    }
}

// ---------------- silu(G)*U in place (G), float4; covers experts 0..NE ----------------
__global__ void silumul_kernel()
{
    int e = blockIdx.y;
    int row = blockIdx.x;
    if (row >= g_cnt[e]) return;
    float4* gp = (float4*)(g_G + ((size_t)e * TCAP + row) * I_DIM);
    const float4* up = (const float4*)(g_U + ((size_t)e * TCAP + row) * I_DIM);
    int i = threadIdx.x;
    float4 g = gp[i];
    float4 u = up[i];
    g.x = (g.x / (1.f + __expf(-g.x))) * u.x;
    g.y = (g.y / (1.f + __expf(-g.y))) * u.y;
    g.z = (g.z / (1.f + __expf(-g.z))) * u.z;
    g.w = (g.w / (1.f + __expf(-g.w))) * u.w;
    gp[i] = g;
}

// ---------------- shared-expert sigmoid gate -> asg_w[NE] ----------------
__global__ void sgate_kernel(const float* __restrict__ segw)
{
    int warp = threadIdx.x >> 5, lane = threadIdx.x & 31;
    int t = blockIdx.x * 8 + warp;
    const float* xr = g_x2 + (size_t)t * H_DIM;
    float a = 0.f;
    for (int k = lane; k < H_DIM; k += 32) a += xr[k] * segw[k];
    #pragma unroll
    for (int off = 16; off; off >>= 1) a += __shfl_xor_sync(0xffffffffu, a, off);
    if (lane == 0) g_asg_w[NE * TCAP + t] = 1.f / (1.f + expf(-a));
}

// ---------------- final combine ----------------
__global__ void combine_kernel(float* __restrict__ out)
{
    int i = blockIdx.x * blockDim.x + threadIdx.x;
    if (i < T_TOK * H_DIM)
        out[i] = g_resid[i] + g_moe[i];
}

// ---------------- aux loss ----------------
__global__ void aux_kernel(float* __restrict__ out_aux)
{
    __shared__ float sm[256];
    int tid = threadIdx.x;
    int e = tid & 7;
    int chunk = tid >> 3;
    float s = 0.f;
    for (int t = chunk; t < T_TOK; t += 32) s += g_probs[t * 8 + e];
    sm[tid] = s;
    __syncthreads();
    for (int st = 16; st >= 1; st >>= 1) {
        if (chunk < st) sm[tid] += sm[tid + st * 8];
        __syncthreads();
    }
    if (tid == 0) {
        float aux = 0.f;
        #pragma unroll
        for (int i = 0; i < 8; i++) {
            float m = sm[i] / (float)T_TOK - 0.125f;
            aux += m * m;
        }
        out_aux[0] = aux / 8.f;
    }
}

// ---------------- launch ----------------
extern "C" void kernel_launch(void* const* d_in, const int* in_sizes, int n_in,
                              void* d_out, int out_size)
{
    const float* hidden = (const float*)d_in[0];
    const int*   pos    = (const int*)d_in[2];
    const float* ln1    = (const float*)d_in[3];
    const float* ln2    = (const float*)d_in[4];
    const float* wq     = (const float*)d_in[5];
    const float* wk     = (const float*)d_in[6];
    const float* wv     = (const float*)d_in[7];
    const float* wo     = (const float*)d_in[8];
    const float* rw     = (const float*)d_in[9];
    const float* egw    = (const float*)d_in[10];
    const float* euw    = (const float*)d_in[11];
    const float* edw    = (const float*)d_in[12];
    const float* sgw    = (const float*)d_in[13];
    const float* suw    = (const float*)d_in[14];
    const float* sdw    = (const float*)d_in[15];
    const float* segw   = (const float*)d_in[16];
    float* out = (float*)d_out;

    float *x1, *qkv, *attn, *resid, *x2, *moe, *G, *U, *asw, *wqkv;
    int *cnt, *ast;
    cudaGetSymbolAddress((void**)&x1, g_x1);
    cudaGetSymbolAddress((void**)&qkv, g_qkv);
    cudaGetSymbolAddress((void**)&attn, g_attn);
    cudaGetSymbolAddress((void**)&resid, g_resid);
    cudaGetSymbolAddress((void**)&x2, g_x2);
    cudaGetSymbolAddress((void**)&moe, g_moe);
    cudaGetSymbolAddress((void**)&G, g_G);
    cudaGetSymbolAddress((void**)&U, g_U);
    cudaGetSymbolAddress((void**)&cnt, g_cnt);
    cudaGetSymbolAddress((void**)&ast, g_asg_tok);
    cudaGetSymbolAddress((void**)&asw, g_asg_w);
    cudaGetSymbolAddress((void**)&wqkv, g_wqkv);

    cudaFuncSetAttribute((const void*)attn_tc_kernel,
                         cudaFuncAttributeMaxDynamicSharedMemorySize, ATT_SMEM);

    zero_kernel<<<(T_TOK * H_DIM + 255) / 256, 256>>>();
    concat_qkv_w<<<(H_DIM * QKV_N + 255) / 256, 256>>>(wq, wk, wv);

    // attention block
    rmsnorm_kernel<<<T_TOK, 256>>>(hidden, ln1, x1);
    gemm_tc<0, 0><<<dim3(12, 16), 256>>>(x1, wqkv, qkv, nullptr, nullptr, nullptr, nullptr,
                                         nullptr, nullptr, nullptr, nullptr, T_TOK, QKV_N, 1024);
    rope_kernel<<<T_TOK, 256>>>(pos);
    attn_tc_kernel<<<dim3(8, NH, B_SZ), 256, ATT_SMEM>>>();
    gemm_tc<1, 0><<<dim3(8, 16), 256>>>(attn, wo, resid, hidden, nullptr, nullptr, nullptr,
                                        nullptr, nullptr, nullptr, nullptr, T_TOK, 1024, 1024);

    // MoE block (shared expert folded in as expert NE)
    rmsnorm_kernel<<<T_TOK, 256>>>(resid, ln2, x2);
    router_kernel<<<T_TOK / 8, 256>>>(rw);
    sgate_kernel<<<T_TOK / 8, 256>>>(segw);
    gemm_tc<2, 1><<<dim3(8, 16, (NE + 1) * 2), 256>>>(x2, egw, G, nullptr, cnt, ast, nullptr,
                                                      euw, U, sgw, suw, TCAP, 1024, 1024);
    silumul_kernel<<<dim3(TCAP, NE + 1), 256>>>();
    gemm_tc<3, 0><<<dim3(8, 16, NE + 1), 256>>>(G, edw, moe, nullptr, cnt, ast, asw,
                                                nullptr, nullptr, sdw, nullptr, TCAP, 1024, 1024);

    combine_kernel<<<(T_TOK * H_DIM + 255) / 256, 256>>>(out);
    if (out_size > T_TOK * H_DIM)
        aux_kernel<<<1, 256>>>(out + (out_size - 1));
}